// round 5
// baseline (speedup 1.0000x reference)
#include <cstdint>
#include <cuda_runtime.h>
#include <mma.h>

using namespace nvcuda;

#define OUT_F  2048
#define IN_F   2048
#define NNZ    209715
#define TOKENS 16384

#define BM 128
#define BN 128
#define BK 32
#define KITERS (IN_F / BK)     // 64
#define NSTAGE 3
#define LDSA 36                // 32 + 4 pad: (4*row + col) % 32 conflict-free
#define TILE_FLOATS (128 * LDSA)           // per A or B tile
#define STAGE_FLOATS (2 * TILE_FLOATS)
#define SMEM_BYTES (NSTAGE * STAGE_FLOATS * 4)   // 110,592 B

// Scratch (device globals: no allocation allowed).
__device__ float g_W[(size_t)OUT_F * IN_F];          // 16 MB dequant+scatter weight
__device__ float g_X[(size_t)TOKENS * IN_F];         // 134 MB tf32-rounded x

__device__ __forceinline__ float to_tf32(float v) {
    float r;
    asm("cvt.rna.tf32.f32 %0, %1;" : "=f"(r) : "f"(v));
    return r;
}

// ---------------------------------------------------------------------------
// Kernel 1: dequantize int4 base into g_W (fp32; rounded later after scatter).
// ---------------------------------------------------------------------------
__global__ void dequant_kernel(const int* __restrict__ packed,
                               const float* __restrict__ scales) {
    int idx = blockIdx.x * blockDim.x + threadIdx.x;   // over OUT_F * IN_F/2
    const int total = OUT_F * (IN_F / 2);
    if (idx >= total) return;
    int o = idx >> 10;                                 // IN_F/2 == 1024
    int p = packed[idx];
    float s = scales[o];
    float2 v;
    v.x = (float)((p & 0xF) - 8) * s;
    v.y = (float)(((p >> 4) & 0xF) - 8) * s;
    reinterpret_cast<float2*>(g_W)[idx] = v;
}

// ---------------------------------------------------------------------------
// Kernel 2: scatter COO residual (duplicates accumulate -> atomicAdd)
// ---------------------------------------------------------------------------
__global__ void scatter_kernel(const float* __restrict__ vals,
                               const int* __restrict__ rows,
                               const int* __restrict__ cols) {
    int i = blockIdx.x * blockDim.x + threadIdx.x;
    if (i >= NNZ) return;
    atomicAdd(&g_W[(size_t)rows[i] * IN_F + cols[i]], vals[i]);
}

// ---------------------------------------------------------------------------
// Kernel 3a: round W in place to tf32. 3b: round x into g_X.
// ---------------------------------------------------------------------------
__global__ void round_w_kernel() {
    int i = blockIdx.x * blockDim.x + threadIdx.x;     // float4 index
    float4 v = reinterpret_cast<float4*>(g_W)[i];
    v.x = to_tf32(v.x); v.y = to_tf32(v.y);
    v.z = to_tf32(v.z); v.w = to_tf32(v.w);
    reinterpret_cast<float4*>(g_W)[i] = v;
}
__global__ void round_x_kernel(const float* __restrict__ x) {
    size_t i = (size_t)blockIdx.x * blockDim.x + threadIdx.x;  // float4 index
    float4 v = reinterpret_cast<const float4*>(x)[i];
    v.x = to_tf32(v.x); v.y = to_tf32(v.y);
    v.z = to_tf32(v.z); v.w = to_tf32(v.w);
    reinterpret_cast<float4*>(g_X)[i] = v;
}

// ---------------------------------------------------------------------------
// GEMM: out[t,o] = sum_i X[t,i] * W[o,i]; tf32 wmma, 128x128 tile, BK=32,
// 3-stage cp.async pipeline, 8 warps (2x4), warp tile 64x32.
// Inputs pre-rounded to tf32 -> no in-loop conversions.
// ---------------------------------------------------------------------------
__device__ __forceinline__ void cpasync16(void* smem, const void* gmem) {
    unsigned s = (unsigned)__cvta_generic_to_shared(smem);
    asm volatile("cp.async.cg.shared.global [%0], [%1], 16;" :: "r"(s), "l"(gmem));
}

extern __shared__ float smf[];

__device__ __forceinline__ void load_stage(float* stg, const float* gA,
                                           const float* gB, int k0, int tid) {
    // A tile: 128 rows x 32 floats = 1024 x 16B chunks; same for B.
    #pragma unroll
    for (int i = 0; i < 4; i++) {
        int idx = i * 256 + tid;          // 0..1023
        int row = idx >> 3;               // 0..127
        int ch  = (idx & 7) * 4;          // float offset within 32
        float* sa = stg + row * LDSA + ch;
        cpasync16(sa,               gA + (size_t)row * IN_F + k0 + ch);
        cpasync16(sa + TILE_FLOATS, gB + (size_t)row * IN_F + k0 + ch);
    }
}

__global__ __launch_bounds__(256, 2)
void gemm_kernel(float* __restrict__ out) {
    const int tid  = threadIdx.x;
    const int warp = tid >> 5;
    const int wm   = warp >> 2;           // 0..1
    const int wn   = warp & 3;            // 0..3

    const int m0 = blockIdx.y * BM;
    const int n0 = blockIdx.x * BN;

    const float* gA = g_X + (size_t)m0 * IN_F;
    const float* gB = g_W + (size_t)n0 * IN_F;

    wmma::fragment<wmma::accumulator, 16, 16, 8, float> acc[4][2];
    #pragma unroll
    for (int i = 0; i < 4; i++)
        #pragma unroll
        for (int j = 0; j < 2; j++)
            wmma::fill_fragment(acc[i][j], 0.0f);

    #pragma unroll
    for (int s = 0; s < NSTAGE; s++) {
        load_stage(smf + s * STAGE_FLOATS, gA, gB, s * BK, tid);
        asm volatile("cp.async.commit_group;" ::: "memory");
    }

    for (int kt = 0; kt < KITERS; kt++) {
        const float* sA = smf + (kt % NSTAGE) * STAGE_FLOATS;
        const float* sB = sA + TILE_FLOATS;

        if (kt < KITERS - 2)       asm volatile("cp.async.wait_group 2;" ::: "memory");
        else if (kt == KITERS - 2) asm volatile("cp.async.wait_group 1;" ::: "memory");
        else                       asm volatile("cp.async.wait_group 0;" ::: "memory");
        __syncthreads();

        #pragma unroll
        for (int ks = 0; ks < 4; ks++) {
            const int kk = ks * 8;
            wmma::fragment<wmma::matrix_a, 16, 16, 8,
                           wmma::precision::tf32, wmma::row_major> af[4];
            wmma::fragment<wmma::matrix_b, 16, 16, 8,
                           wmma::precision::tf32, wmma::col_major> bf[2];
            #pragma unroll
            for (int i = 0; i < 4; i++)
                wmma::load_matrix_sync(af[i], sA + (wm * 64 + i * 16) * LDSA + kk, LDSA);
            #pragma unroll
            for (int j = 0; j < 2; j++)
                wmma::load_matrix_sync(bf[j], sB + (wn * 32 + j * 16) * LDSA + kk, LDSA);
            #pragma unroll
            for (int i = 0; i < 4; i++)
                #pragma unroll
                for (int j = 0; j < 2; j++)
                    wmma::mma_sync(acc[i][j], af[i], bf[j], acc[i][j]);
        }
        __syncthreads();   // all warps done reading buffer before refill

        if (kt + NSTAGE < KITERS) {
            load_stage(smf + (kt % NSTAGE) * STAGE_FLOATS, gA, gB,
                       (kt + NSTAGE) * BK, tid);
            asm volatile("cp.async.commit_group;" ::: "memory");
        }
    }

    #pragma unroll
    for (int i = 0; i < 4; i++)
        #pragma unroll
        for (int j = 0; j < 2; j++) {
            float* dst = out + (size_t)(m0 + wm * 64 + i * 16) * OUT_F
                             + n0 + wn * 32 + j * 16;
            wmma::store_matrix_sync(dst, acc[i][j], OUT_F, wmma::mem_row_major);
        }
}

// ---------------------------------------------------------------------------
// Inputs (metadata order):
//   0: x float32 [4,4096,2048]   1: base_packed int32 [2048,1024]
//   2: scales float32 [2048]     3: ortho_vals float32 [209715]
//   4: ortho_rows int32          5: ortho_cols int32
// output: float32 [16384, 2048]
// ---------------------------------------------------------------------------
extern "C" void kernel_launch(void* const* d_in, const int* in_sizes, int n_in,
                              void* d_out, int out_size) {
    const float* x      = (const float*)d_in[0];
    const int*   packed = (const int*)  d_in[1];
    const float* scales = (const float*)d_in[2];
    const float* ovals  = (const float*)d_in[3];
    const int*   orows  = (const int*)  d_in[4];
    const int*   ocols  = (const int*)  d_in[5];
    float*       out    = (float*)d_out;

    dequant_kernel<<<(OUT_F * (IN_F / 2) + 255) / 256, 256>>>(packed, scales);
    scatter_kernel<<<(NNZ + 255) / 256, 256>>>(ovals, orows, ocols);
    round_w_kernel<<<(OUT_F * IN_F / 4) / 256, 256>>>();
    round_x_kernel<<<((size_t)TOKENS * IN_F / 4) / 256, 256>>>(x);

    cudaFuncSetAttribute(gemm_kernel,
                         cudaFuncAttributeMaxDynamicSharedMemorySize, SMEM_BYTES);
    dim3 grid(OUT_F / BN, TOKENS / BM);   // x-fastest: 16 n-tiles share x tile in L2
    gemm_kernel<<<grid, 256, SMEM_BYTES>>>(out);
}

// round 6
// speedup vs baseline: 3.4972x; 3.4972x over previous
#include <cstdint>
#include <cuda_runtime.h>
#include <cuda_fp16.h>
#include <mma.h>

using namespace nvcuda;

#define OUT_F  2048
#define IN_F   2048
#define NNZ    209715
#define TOKENS 16384

#define BM 128
#define BN 128
#define BK 32
#define KITERS (IN_F / BK)     // 64
#define NSTAGE 3
#define LDH 40                 // halves per smem row: 32 + 8 pad (80B, 16B-mult)
#define TILE_HALVES (128 * LDH)
#define STAGE_HALVES (2 * TILE_HALVES)
#define SMEM_BYTES (NSTAGE * STAGE_HALVES * 2)   // 61,440 B

// Scratch (device globals: no allocation allowed).
__device__ float  g_W [(size_t)OUT_F * IN_F];    // fp32 dequant+scatter staging
__device__ __half g_Wh[(size_t)OUT_F * IN_F];    // fp16 weight (8 MB)
__device__ __half g_Xh[(size_t)TOKENS * IN_F];   // fp16 activations (67 MB)

// ---------------------------------------------------------------------------
// Kernel 1: dequantize int4 base into g_W (fp32; fp16 after scatter).
// ---------------------------------------------------------------------------
__global__ void dequant_kernel(const int* __restrict__ packed,
                               const float* __restrict__ scales) {
    int idx = blockIdx.x * blockDim.x + threadIdx.x;   // over OUT_F * IN_F/2
    const int total = OUT_F * (IN_F / 2);
    if (idx >= total) return;
    int o = idx >> 10;                                 // IN_F/2 == 1024
    int p = packed[idx];
    float s = scales[o];
    float2 v;
    v.x = (float)((p & 0xF) - 8) * s;
    v.y = (float)(((p >> 4) & 0xF) - 8) * s;
    reinterpret_cast<float2*>(g_W)[idx] = v;
}

// ---------------------------------------------------------------------------
// Kernel 2: scatter COO residual (duplicates accumulate -> fp32 atomicAdd)
// ---------------------------------------------------------------------------
__global__ void scatter_kernel(const float* __restrict__ vals,
                               const int* __restrict__ rows,
                               const int* __restrict__ cols) {
    int i = blockIdx.x * blockDim.x + threadIdx.x;
    if (i >= NNZ) return;
    atomicAdd(&g_W[(size_t)rows[i] * IN_F + cols[i]], vals[i]);
}

// ---------------------------------------------------------------------------
// Kernel 3a: W fp32 -> fp16.  3b: x fp32 -> fp16.
// ---------------------------------------------------------------------------
__global__ void convert_w_kernel() {
    int i = blockIdx.x * blockDim.x + threadIdx.x;     // float4 index
    float4 v = reinterpret_cast<const float4*>(g_W)[i];
    __half2 h0 = __floats2half2_rn(v.x, v.y);
    __half2 h1 = __floats2half2_rn(v.z, v.w);
    reinterpret_cast<__half2*>(g_Wh)[i * 2 + 0] = h0;
    reinterpret_cast<__half2*>(g_Wh)[i * 2 + 1] = h1;
}
__global__ void convert_x_kernel(const float* __restrict__ x) {
    size_t i = (size_t)blockIdx.x * blockDim.x + threadIdx.x;  // float4 index
    float4 v = reinterpret_cast<const float4*>(x)[i];
    __half2 h0 = __floats2half2_rn(v.x, v.y);
    __half2 h1 = __floats2half2_rn(v.z, v.w);
    reinterpret_cast<__half2*>(g_Xh)[i * 2 + 0] = h0;
    reinterpret_cast<__half2*>(g_Xh)[i * 2 + 1] = h1;
}

// ---------------------------------------------------------------------------
// GEMM: out[t,o] = sum_i X[t,i] * W[o,i]; fp16 wmma (16x16x16), fp32 acc.
// 128x128 CTA tile, BK=32, 3-stage cp.async, 8 warps (2x4), warp tile 64x32.
// ---------------------------------------------------------------------------
__device__ __forceinline__ void cpasync16(void* smem, const void* gmem) {
    unsigned s = (unsigned)__cvta_generic_to_shared(smem);
    asm volatile("cp.async.cg.shared.global [%0], [%1], 16;" :: "r"(s), "l"(gmem));
}

extern __shared__ __half smh[];

__device__ __forceinline__ void load_stage(__half* stg, const __half* gA,
                                           const __half* gB, int k0, int tid) {
    // per tile: 128 rows x 32 halves (64B) = 512 x 16B chunks; A+B = 1024.
    #pragma unroll
    for (int i = 0; i < 2; i++) {
        int idx = i * 256 + tid;          // 0..511
        int row = idx >> 2;               // 0..127
        int ch  = (idx & 3) * 8;          // half offset within 32
        __half* sa = stg + row * LDH + ch;
        cpasync16(sa,               gA + (size_t)row * IN_F + k0 + ch);
        cpasync16(sa + TILE_HALVES, gB + (size_t)row * IN_F + k0 + ch);
    }
}

__global__ __launch_bounds__(256, 2)
void gemm_kernel(float* __restrict__ out) {
    const int tid  = threadIdx.x;
    const int warp = tid >> 5;
    const int wm   = warp >> 2;           // 0..1
    const int wn   = warp & 3;            // 0..3

    const int m0 = blockIdx.y * BM;
    const int n0 = blockIdx.x * BN;

    const __half* gA = g_Xh + (size_t)m0 * IN_F;
    const __half* gB = g_Wh + (size_t)n0 * IN_F;

    wmma::fragment<wmma::accumulator, 16, 16, 16, float> acc[4][2];
    #pragma unroll
    for (int i = 0; i < 4; i++)
        #pragma unroll
        for (int j = 0; j < 2; j++)
            wmma::fill_fragment(acc[i][j], 0.0f);

    #pragma unroll
    for (int s = 0; s < NSTAGE; s++) {
        load_stage(smh + s * STAGE_HALVES, gA, gB, s * BK, tid);
        asm volatile("cp.async.commit_group;" ::: "memory");
    }

    for (int kt = 0; kt < KITERS; kt++) {
        const __half* sA = smh + (kt % NSTAGE) * STAGE_HALVES;
        const __half* sB = sA + TILE_HALVES;

        if (kt < KITERS - 2)       asm volatile("cp.async.wait_group 2;" ::: "memory");
        else if (kt == KITERS - 2) asm volatile("cp.async.wait_group 1;" ::: "memory");
        else                       asm volatile("cp.async.wait_group 0;" ::: "memory");
        __syncthreads();

        #pragma unroll
        for (int ks = 0; ks < 2; ks++) {    // two K=16 steps per BK=32
            const int kk = ks * 16;
            wmma::fragment<wmma::matrix_a, 16, 16, 16, __half, wmma::row_major> af[4];
            wmma::fragment<wmma::matrix_b, 16, 16, 16, __half, wmma::col_major> bf[2];
            #pragma unroll
            for (int i = 0; i < 4; i++)
                wmma::load_matrix_sync(af[i], sA + (wm * 64 + i * 16) * LDH + kk, LDH);
            #pragma unroll
            for (int j = 0; j < 2; j++)
                wmma::load_matrix_sync(bf[j], sB + (wn * 32 + j * 16) * LDH + kk, LDH);
            #pragma unroll
            for (int i = 0; i < 4; i++)
                #pragma unroll
                for (int j = 0; j < 2; j++)
                    wmma::mma_sync(acc[i][j], af[i], bf[j], acc[i][j]);
        }
        __syncthreads();

        if (kt + NSTAGE < KITERS) {
            load_stage(smh + (kt % NSTAGE) * STAGE_HALVES, gA, gB,
                       (kt + NSTAGE) * BK, tid);
            asm volatile("cp.async.commit_group;" ::: "memory");
        }
    }

    #pragma unroll
    for (int i = 0; i < 4; i++)
        #pragma unroll
        for (int j = 0; j < 2; j++) {
            float* dst = out + (size_t)(m0 + wm * 64 + i * 16) * OUT_F
                             + n0 + wn * 32 + j * 16;
            wmma::store_matrix_sync(dst, acc[i][j], OUT_F, wmma::mem_row_major);
        }
}

// ---------------------------------------------------------------------------
// Inputs (metadata order):
//   0: x float32 [4,4096,2048]   1: base_packed int32 [2048,1024]
//   2: scales float32 [2048]     3: ortho_vals float32 [209715]
//   4: ortho_rows int32          5: ortho_cols int32
// output: float32 [16384, 2048]
// ---------------------------------------------------------------------------
extern "C" void kernel_launch(void* const* d_in, const int* in_sizes, int n_in,
                              void* d_out, int out_size) {
    const float* x      = (const float*)d_in[0];
    const int*   packed = (const int*)  d_in[1];
    const float* scales = (const float*)d_in[2];
    const float* ovals  = (const float*)d_in[3];
    const int*   orows  = (const int*)  d_in[4];
    const int*   ocols  = (const int*)  d_in[5];
    float*       out    = (float*)d_out;

    dequant_kernel<<<(OUT_F * (IN_F / 2) + 255) / 256, 256>>>(packed, scales);
    scatter_kernel<<<(NNZ + 255) / 256, 256>>>(ovals, orows, ocols);
    convert_w_kernel<<<(OUT_F * IN_F / 4) / 256, 256>>>();
    convert_x_kernel<<<((size_t)TOKENS * IN_F / 4) / 256, 256>>>(x);

    cudaFuncSetAttribute(gemm_kernel,
                         cudaFuncAttributeMaxDynamicSharedMemorySize, SMEM_BYTES);
    dim3 grid(OUT_F / BN, TOKENS / BM);   // x-fastest: n-tiles share x tile in L2
    gemm_kernel<<<grid, 256, SMEM_BYTES>>>(out);
}

// round 9
// speedup vs baseline: 4.2072x; 1.2030x over previous
#include <cstdint>
#include <cuda_runtime.h>
#include <cuda_fp16.h>
#include <mma.h>

using namespace nvcuda;

#define OUT_F  2048
#define IN_F   2048
#define NNZ    209715
#define TOKENS 16384

#define BM 128
#define BN 128
#define BK 32
#define KITERS (IN_F / BK)     // 64
#define NSTAGE 4
#define LDH 40                 // halves per smem row: 32 + 8 pad (80B, 16B-mult)
#define TILE_HALVES (128 * LDH)
#define STAGE_HALVES (2 * TILE_HALVES)
#define SMEM_BYTES (NSTAGE * STAGE_HALVES * 2)   // 81,920 B per CTA

// Scratch (device globals: no allocation allowed).
__device__ float  g_W [(size_t)OUT_F * IN_F];    // fp32 dequant+scatter staging
__device__ __half g_Wh[(size_t)OUT_F * IN_F];    // fp16 weight (8 MB)
__device__ __half g_Xh[(size_t)TOKENS * IN_F];   // fp16 activations (67 MB)

// ---------------------------------------------------------------------------
// Kernel 1: dequantize int4 base into g_W (fp32; fp16 after scatter).
// ---------------------------------------------------------------------------
__global__ void dequant_kernel(const int* __restrict__ packed,
                               const float* __restrict__ scales) {
    int idx = blockIdx.x * blockDim.x + threadIdx.x;   // over OUT_F * IN_F/2
    const int total = OUT_F * (IN_F / 2);
    if (idx >= total) return;
    int o = idx >> 10;                                 // IN_F/2 == 1024
    int p = packed[idx];
    float s = scales[o];
    float2 v;
    v.x = (float)((p & 0xF) - 8) * s;
    v.y = (float)(((p >> 4) & 0xF) - 8) * s;
    reinterpret_cast<float2*>(g_W)[idx] = v;
}

// ---------------------------------------------------------------------------
// Kernel 2: scatter COO residual (duplicates accumulate -> fp32 atomicAdd)
// ---------------------------------------------------------------------------
__global__ void scatter_kernel(const float* __restrict__ vals,
                               const int* __restrict__ rows,
                               const int* __restrict__ cols) {
    int i = blockIdx.x * blockDim.x + threadIdx.x;
    if (i >= NNZ) return;
    atomicAdd(&g_W[(size_t)rows[i] * IN_F + cols[i]], vals[i]);
}

// ---------------------------------------------------------------------------
// Kernel 3a: W fp32 -> fp16.  3b: x fp32 -> fp16.
// ---------------------------------------------------------------------------
__global__ void convert_w_kernel() {
    int i = blockIdx.x * blockDim.x + threadIdx.x;     // float4 index
    float4 v = reinterpret_cast<const float4*>(g_W)[i];
    __half2 h0 = __floats2half2_rn(v.x, v.y);
    __half2 h1 = __floats2half2_rn(v.z, v.w);
    reinterpret_cast<__half2*>(g_Wh)[i * 2 + 0] = h0;
    reinterpret_cast<__half2*>(g_Wh)[i * 2 + 1] = h1;
}
__global__ void convert_x_kernel(const float* __restrict__ x) {
    size_t i = (size_t)blockIdx.x * blockDim.x + threadIdx.x;  // float4 index
    float4 v = reinterpret_cast<const float4*>(x)[i];
    __half2 h0 = __floats2half2_rn(v.x, v.y);
    __half2 h1 = __floats2half2_rn(v.z, v.w);
    reinterpret_cast<__half2*>(g_Xh)[i * 2 + 0] = h0;
    reinterpret_cast<__half2*>(g_Xh)[i * 2 + 1] = h1;
}

// ---------------------------------------------------------------------------
// GEMM: out[t,o] = sum_i X[t,i] * W[o,i]; fp16 wmma (16x16x16), fp32 acc.
// CTA tile 128x128, BK=32, 4-stage cp.async, 4 warps (2x2), warp tile 64x64.
// One __syncthreads per K-iteration (CUTLASS-style slot reuse).
// ---------------------------------------------------------------------------
__device__ __forceinline__ void cpasync16(void* smem, const void* gmem) {
    unsigned s = (unsigned)__cvta_generic_to_shared(smem);
    asm volatile("cp.async.cg.shared.global [%0], [%1], 16;" :: "r"(s), "l"(gmem));
}

extern __shared__ __half smh[];

__device__ __forceinline__ void load_stage(__half* stg, const __half* gA,
                                           const __half* gB, int k0, int tid) {
    // per tile: 128 rows x 32 halves (64B) = 512 x 16B chunks; A+B = 1024.
    // 128 threads -> 8 chunks each (4 A + 4 B).
    #pragma unroll
    for (int i = 0; i < 4; i++) {
        int idx = i * 128 + tid;          // 0..511
        int row = idx >> 2;               // 0..127
        int ch  = (idx & 3) * 8;          // half offset within 32
        __half* sa = stg + row * LDH + ch;
        cpasync16(sa,               gA + (size_t)row * IN_F + k0 + ch);
        cpasync16(sa + TILE_HALVES, gB + (size_t)row * IN_F + k0 + ch);
    }
}

__global__ __launch_bounds__(128, 2)
void gemm_kernel(float* __restrict__ out) {
    const int tid  = threadIdx.x;
    const int warp = tid >> 5;
    const int wm   = warp >> 1;           // 0..1
    const int wn   = warp & 1;            // 0..1

    const int m0 = blockIdx.y * BM;
    const int n0 = blockIdx.x * BN;

    const __half* gA = g_Xh + (size_t)m0 * IN_F;
    const __half* gB = g_Wh + (size_t)n0 * IN_F;

    wmma::fragment<wmma::accumulator, 16, 16, 16, float> acc[4][4];
    #pragma unroll
    for (int i = 0; i < 4; i++)
        #pragma unroll
        for (int j = 0; j < 4; j++)
            wmma::fill_fragment(acc[i][j], 0.0f);

    // prologue: fill NSTAGE-1 stages
    #pragma unroll
    for (int s = 0; s < NSTAGE - 1; s++) {
        load_stage(smh + s * STAGE_HALVES, gA, gB, s * BK, tid);
        asm volatile("cp.async.commit_group;" ::: "memory");
    }

    for (int kt = 0; kt < KITERS; kt++) {
        // stage kt must be resident; outstanding groups are {kt, kt+1, kt+2}∩range
        if (kt < KITERS - 2)       asm volatile("cp.async.wait_group 2;" ::: "memory");
        else if (kt == KITERS - 2) asm volatile("cp.async.wait_group 1;" ::: "memory");
        else                       asm volatile("cp.async.wait_group 0;" ::: "memory");
        __syncthreads();   // also proves all warps finished compute of kt-1
                           // -> slot (kt-1)%NSTAGE == (kt+3)%NSTAGE is reusable

        if (kt + NSTAGE - 1 < KITERS) {
            load_stage(smh + ((kt + NSTAGE - 1) % NSTAGE) * STAGE_HALVES,
                       gA, gB, (kt + NSTAGE - 1) * BK, tid);
            asm volatile("cp.async.commit_group;" ::: "memory");
        }

        const __half* sA = smh + (kt % NSTAGE) * STAGE_HALVES;
        const __half* sB = sA + TILE_HALVES;

        #pragma unroll
        for (int ks = 0; ks < 2; ks++) {    // two K=16 steps per BK=32
            const int kk = ks * 16;
            wmma::fragment<wmma::matrix_a, 16, 16, 16, __half, wmma::row_major> af[4];
            wmma::fragment<wmma::matrix_b, 16, 16, 16, __half, wmma::col_major> bf[4];
            #pragma unroll
            for (int i = 0; i < 4; i++)
                wmma::load_matrix_sync(af[i], sA + (wm * 64 + i * 16) * LDH + kk, LDH);
            #pragma unroll
            for (int j = 0; j < 4; j++)
                wmma::load_matrix_sync(bf[j], sB + (wn * 64 + j * 16) * LDH + kk, LDH);
            #pragma unroll
            for (int i = 0; i < 4; i++)
                #pragma unroll
                for (int j = 0; j < 4; j++)
                    wmma::mma_sync(acc[i][j], af[i], bf[j], acc[i][j]);
        }
    }

    #pragma unroll
    for (int i = 0; i < 4; i++)
        #pragma unroll
        for (int j = 0; j < 4; j++) {
            float* dst = out + (size_t)(m0 + wm * 64 + i * 16) * OUT_F
                             + n0 + wn * 64 + j * 16;
            wmma::store_matrix_sync(dst, acc[i][j], OUT_F, wmma::mem_row_major);
        }
}

// ---------------------------------------------------------------------------
// Inputs (metadata order):
//   0: x float32 [4,4096,2048]   1: base_packed int32 [2048,1024]
//   2: scales float32 [2048]     3: ortho_vals float32 [209715]
//   4: ortho_rows int32          5: ortho_cols int32
// output: float32 [16384, 2048]
// ---------------------------------------------------------------------------
extern "C" void kernel_launch(void* const* d_in, const int* in_sizes, int n_in,
                              void* d_out, int out_size) {
    const float* x      = (const float*)d_in[0];
    const int*   packed = (const int*)  d_in[1];
    const float* scales = (const float*)d_in[2];
    const float* ovals  = (const float*)d_in[3];
    const int*   orows  = (const int*)  d_in[4];
    const int*   ocols  = (const int*)  d_in[5];
    float*       out    = (float*)d_out;

    dequant_kernel<<<(OUT_F * (IN_F / 2) + 255) / 256, 256>>>(packed, scales);
    scatter_kernel<<<(NNZ + 255) / 256, 256>>>(ovals, orows, ocols);
    convert_w_kernel<<<(OUT_F * IN_F / 4) / 256, 256>>>();
    convert_x_kernel<<<((size_t)TOKENS * IN_F / 4) / 256, 256>>>(x);

    cudaFuncSetAttribute(gemm_kernel,
                         cudaFuncAttributeMaxDynamicSharedMemorySize, SMEM_BYTES);
    dim3 grid(OUT_F / BN, TOKENS / BM);   // x-fastest: n-tiles share x tile in L2
    gemm_kernel<<<grid, 128, SMEM_BYTES>>>(out);
}